// round 10
// baseline (speedup 1.0000x reference)
#include <cuda_runtime.h>

#define QPB 2
#define LN_EPS 1e-5f
#define Z_EPS  1e-5f

// Transposed-weight scratch (written by prologue kernel each launch).
__device__ float g_WoutT[256 * 256];   // [c][k]
__device__ float g_pew2T[256 * 256];   // [c][k]
__device__ float g_WqeT [256 * 64];    // [c][k]  (c=0..255, k=0..63)
__device__ float g_WfinT[64 * 256];    // [c][k]  (c=0..63,  k=0..255)

__global__ __launch_bounds__(256)
void transpose_weights(const float* __restrict__ Wout, const float* __restrict__ pew2,
                       const float* __restrict__ Wqe,  const float* __restrict__ Wfin) {
    const int idx = blockIdx.x * 256 + threadIdx.x;   // 0 .. 65535
    {
        const int c = idx >> 8, k = idx & 255;        // 256x256
        g_WoutT[idx] = Wout[k * 256 + c];
        g_pew2T[idx] = pew2[k * 256 + c];
    }
    if (idx < 16384) {
        const int c = idx >> 6, k = idx & 63;         // 256x64 out
        g_WqeT[idx] = Wqe[k * 256 + c];
        const int c2 = idx >> 8, k2 = idx & 255;      // 64x256 out
        g_WfinT[idx] = Wfin[k2 * 64 + c2];
    }
}

// Block-wide sum of a float4 across 256 threads.
__device__ __forceinline__ float4 blockSum4(float4 v, float4* red) {
    const int tid  = threadIdx.x;
    const int lane = tid & 31, warp = tid >> 5;
    #pragma unroll
    for (int s = 16; s >= 1; s >>= 1) {
        v.x += __shfl_xor_sync(0xffffffffu, v.x, s);
        v.y += __shfl_xor_sync(0xffffffffu, v.y, s);
        v.z += __shfl_xor_sync(0xffffffffu, v.z, s);
        v.w += __shfl_xor_sync(0xffffffffu, v.w, s);
    }
    if (lane == 0) red[warp] = v;
    __syncthreads();
    if (warp == 0) {
        float4 t = (lane < 8) ? red[lane] : make_float4(0.f, 0.f, 0.f, 0.f);
        #pragma unroll
        for (int s = 4; s >= 1; s >>= 1) {
            t.x += __shfl_xor_sync(0xffffffffu, t.x, s);
            t.y += __shfl_xor_sync(0xffffffffu, t.y, s);
            t.z += __shfl_xor_sync(0xffffffffu, t.z, s);
            t.w += __shfl_xor_sync(0xffffffffu, t.w, s);
        }
        if (lane == 0) red[0] = t;
    }
    __syncthreads();
    float4 r = red[0];
    __syncthreads();
    return r;
}

__global__ __launch_bounds__(256)
void detr3d_fused_kernel(
    const float* __restrict__ query, const float* __restrict__ query_pos,
    const float* __restrict__ refp,  const float* __restrict__ l2i,
    const float* __restrict__ f0, const float* __restrict__ f1,
    const float* __restrict__ f2, const float* __restrict__ f3,
    const float* __restrict__ b_qe,
    const float* __restrict__ W_attn, const float* __restrict__ b_attn,
    const float* __restrict__ b_out,
    const float* __restrict__ pe_w1,  const float* __restrict__ pe_b1,
    const float* __restrict__ pe_g1,  const float* __restrict__ pe_be1,
    const float* __restrict__ pe_b2,
    const float* __restrict__ pe_g2,  const float* __restrict__ pe_be2,
    const float* __restrict__ b_fin,
    const float* __restrict__ g_norm, const float* __restrict__ b_norm,
    float* __restrict__ out)
{
    const int qb   = blockIdx.x * QPB;
    const int tid  = threadIdx.x;
    const int lane = tid & 31, warp = tid >> 5;

    __shared__ __align__(16) float sh_q[QPB][64];
    __shared__ float  sh_ref[QPB][3];
    __shared__ float  sh_qe[QPB][256];
    __shared__ __align__(16) float sh_x[QPB][256];  // gather acc; later h
    __shared__ __align__(16) float sh_p[QPB][256];  // pos MLP hidden
    __shared__ float  sh_part[256];                 // W_fin partials
    __shared__ float4 sh_red[8];
    __shared__ float2 sh_fin[4];
    __shared__ float  sh_w[QPB][24];
    __shared__ int4   sh_gi[QPB][6][4];
    __shared__ float4 sh_gw[QPB][6][4];
    __shared__ int    sh_mask[QPB][6];

    // ---- load q = query + query_pos, reference points
    if (tid < QPB * 64) {
        const int j = tid >> 6, c = tid & 63;
        sh_q[j][c] = query[(qb + j) * 64 + c] + query_pos[(qb + j) * 64 + c];
    }
    if (tid >= 128 && tid < 128 + QPB * 3) {
        const int i = tid - 128;
        sh_ref[i / 3][i % 3] = refp[(qb + i / 3) * 3 + i % 3];
    }
    __syncthreads();

    // ---- qe GEMV (64 -> 256) with transposed weights; thread = channel
    float qe[QPB];
    {
        const float4* wt = (const float4*)&g_WqeT[tid * 64];
        const float4* u4 = (const float4*)sh_q[0];
        const float4* v4 = (const float4*)sh_q[1];
        float a0 = 0.f, a1 = 0.f;
        #pragma unroll
        for (int k4 = 0; k4 < 16; k4++) {
            const float4 w = wt[k4];
            const float4 u = u4[k4];
            const float4 v = v4[k4];
            a0 = fmaf(w.x, u.x, a0); a0 = fmaf(w.y, u.y, a0);
            a0 = fmaf(w.z, u.z, a0); a0 = fmaf(w.w, u.w, a0);
            a1 = fmaf(w.x, v.x, a1); a1 = fmaf(w.y, v.y, a1);
            a1 = fmaf(w.z, v.z, a1); a1 = fmaf(w.w, v.w, a1);
        }
        const float b = __ldg(&b_qe[tid]);
        qe[0] = b + a0; qe[1] = b + a1;
        sh_qe[0][tid] = qe[0]; sh_qe[1][tid] = qe[1];
    }

    // ---- projection + tap precompute (threads 0..47; 1 per (j,n,l))
    if (tid < QPB * 24) {
        const int j = tid / 24, r = tid % 24, n = r / 4, l = r % 4;
        const int Hs[4] = { 116, 58, 29, 15 };
        const int Ws[4] = { 200, 100, 50, 25 };
        const float* M = l2i + n * 16;
        const float rx = sh_ref[j][0], ry = sh_ref[j][1], rz = sh_ref[j][2];
        float c0 = M[0] * rx + M[1] * ry + M[2]  * rz + M[3];
        float c1 = M[4] * rx + M[5] * ry + M[6]  * rz + M[7];
        float c2 = M[8] * rx + M[9] * ry + M[10] * rz + M[11];
        bool front = c2 > Z_EPS;
        float zc = fmaxf(c2, Z_EPS);
        float gx = (c0 / zc / 1600.0f - 0.5f) * 2.0f;
        float gy = (c1 / zc / 928.0f  - 0.5f) * 2.0f;
        bool inb = (gx > -1.0f) && (gx < 1.0f) && (gy > -1.0f) && (gy < 1.0f);
        if (l == 0) sh_mask[j][n] = (front && inb) ? 1 : 0;

        const int W = Ws[l], H = Hs[l];
        float x = ((gx + 1.0f) * (float)W - 1.0f) * 0.5f;
        float y = ((gy + 1.0f) * (float)H - 1.0f) * 0.5f;
        float fx0 = floorf(x), fy0 = floorf(y);
        int x0 = (int)fx0, y0 = (int)fy0;
        float wx1 = x - fx0, wx0 = 1.0f - wx1;
        float wy1 = y - fy0, wy0 = 1.0f - wy1;
        float vx0 = (x0 >= 0 && x0 < W) ? 1.0f : 0.0f;
        float vx1 = (x0 + 1 >= 0 && x0 + 1 < W) ? 1.0f : 0.0f;
        float vy0 = (y0 >= 0 && y0 < H) ? 1.0f : 0.0f;
        float vy1 = (y0 + 1 >= 0 && y0 + 1 < H) ? 1.0f : 0.0f;
        int cx0 = min(max(x0, 0), W - 1);
        int cx1 = min(max(x0 + 1, 0), W - 1);
        int cy0 = min(max(y0, 0), H - 1);
        int cy1 = min(max(y0 + 1, 0), H - 1);
        sh_gi[j][n][l] = make_int4(cy0 * W + cx0, cy0 * W + cx1,
                                   cy1 * W + cx0, cy1 * W + cx1);
        sh_gw[j][n][l] = make_float4(wy0 * wx0 * vy0 * vx0, wy0 * wx1 * vy0 * vx1,
                                     wy1 * wx0 * vy1 * vx0, wy1 * wx1 * vy1 * vx1);
    }
    __syncthreads();

    // ---- attw: warp-split GEMV; warp w owns outputs {w, w+8, w+16}
    {
        float acc[3][QPB];
        #pragma unroll
        for (int i = 0; i < 3; i++)
            #pragma unroll
            for (int j = 0; j < QPB; j++) acc[i][j] = 0.0f;
        #pragma unroll
        for (int kk = 0; kk < 8; kk++) {
            const int k = lane + 32 * kk;
            const float q0 = sh_qe[0][k];
            const float q1 = sh_qe[1][k];
            #pragma unroll
            for (int i = 0; i < 3; i++) {
                const float wv = __ldg(&W_attn[k * 24 + warp + 8 * i]);
                acc[i][0] = fmaf(q0, wv, acc[i][0]);
                acc[i][1] = fmaf(q1, wv, acc[i][1]);
            }
        }
        #pragma unroll
        for (int i = 0; i < 3; i++)
            #pragma unroll
            for (int j = 0; j < QPB; j++) {
                #pragma unroll
                for (int s = 16; s >= 1; s >>= 1)
                    acc[i][j] += __shfl_xor_sync(0xffffffffu, acc[i][j], s);
            }
        if (lane == 0) {
            #pragma unroll
            for (int i = 0; i < 3; i++) {
                const int o = warp + 8 * i;
                const float b = __ldg(&b_attn[o]);
                sh_w[0][o] = 1.0f / (1.0f + expf(-(acc[i][0] + b)));
                sh_w[1][o] = 1.0f / (1.0f + expf(-(acc[i][1] + b)));
            }
        }
    }
    __syncthreads();

    // ---- masked bilinear gather (precomputed taps). thread = channel.
    {
        const float* fps[4] = { f0, f1, f2, f3 };
        const int HWs[4] = { 116 * 200, 58 * 100, 29 * 50, 15 * 25 };
        float acc[QPB];
        #pragma unroll
        for (int j = 0; j < QPB; j++) acc[j] = 0.0f;
        #pragma unroll
        for (int j = 0; j < QPB; j++) {
            for (int n = 0; n < 6; n++) {
                if (!sh_mask[j][n]) continue;
                #pragma unroll
                for (int l = 0; l < 4; l++) {
                    const int4   o = sh_gi[j][n][l];
                    const float4 w = sh_gw[j][n][l];
                    const float* fb = fps[l] + (size_t)(n * 256 + tid) * (size_t)HWs[l];
                    float v = w.x * __ldg(fb + o.x)
                            + w.y * __ldg(fb + o.y)
                            + w.z * __ldg(fb + o.z)
                            + w.w * __ldg(fb + o.w);
                    acc[j] = fmaf(sh_w[j][n * 4 + l], v, acc[j]);
                }
            }
        }
        sh_x[0][tid] = acc[0]; sh_x[1][tid] = acc[1];
    }
    __syncthreads();

    // ---- W_out GEMV (256 -> 256), transposed weights, float4, dual accs
    float ov[QPB];
    {
        const float4* wt = (const float4*)&g_WoutT[tid * 256];
        const float4* u4 = (const float4*)sh_x[0];
        const float4* v4 = (const float4*)sh_x[1];
        float a0 = 0.f, b0 = 0.f, a1 = 0.f, b1 = 0.f;
        #pragma unroll 8
        for (int k4 = 0; k4 < 64; k4 += 2) {
            {
                const float4 w = wt[k4], u = u4[k4], v = v4[k4];
                a0 = fmaf(w.x, u.x, a0); a0 = fmaf(w.y, u.y, a0);
                a0 = fmaf(w.z, u.z, a0); a0 = fmaf(w.w, u.w, a0);
                a1 = fmaf(w.x, v.x, a1); a1 = fmaf(w.y, v.y, a1);
                a1 = fmaf(w.z, v.z, a1); a1 = fmaf(w.w, v.w, a1);
            }
            {
                const float4 w = wt[k4 + 1], u = u4[k4 + 1], v = v4[k4 + 1];
                b0 = fmaf(w.x, u.x, b0); b0 = fmaf(w.y, u.y, b0);
                b0 = fmaf(w.z, u.z, b0); b0 = fmaf(w.w, u.w, b0);
                b1 = fmaf(w.x, v.x, b1); b1 = fmaf(w.y, v.y, b1);
                b1 = fmaf(w.z, v.z, b1); b1 = fmaf(w.w, v.w, b1);
            }
        }
        const float b = __ldg(&b_out[tid]);
        ov[0] = b + a0 + b0; ov[1] = b + a1 + b1;
    }

    // ---- positional MLP stage 1: ref @ pe_w1 + pe_b1 -> LN -> relu
    {
        const float w1 = __ldg(&pe_w1[tid]);
        const float w2 = __ldg(&pe_w1[256 + tid]);
        const float w3 = __ldg(&pe_w1[512 + tid]);
        const float b  = __ldg(&pe_b1[tid]);
        float p[QPB];
        #pragma unroll
        for (int j = 0; j < QPB; j++)
            p[j] = b + sh_ref[j][0] * w1 + sh_ref[j][1] * w2 + sh_ref[j][2] * w3;
        float4 s = blockSum4(make_float4(p[0], p[1], p[0]*p[0], p[1]*p[1]), sh_red);
        const float g = __ldg(&pe_g1[tid]), be = __ldg(&pe_be1[tid]);
        {
            float m = s.x * (1.0f / 256.0f);
            float var = s.z * (1.0f / 256.0f) - m * m;
            sh_p[0][tid] = fmaxf((p[0] - m) * rsqrtf(var + LN_EPS) * g + be, 0.0f);
        }
        {
            float m = s.y * (1.0f / 256.0f);
            float var = s.w * (1.0f / 256.0f) - m * m;
            sh_p[1][tid] = fmaxf((p[1] - m) * rsqrtf(var + LN_EPS) * g + be, 0.0f);
        }
    }
    __syncthreads();

    // ---- pe_w2 GEMV (256 -> 256), transposed weights, float4, dual accs
    float p2[QPB];
    {
        const float4* wt = (const float4*)&g_pew2T[tid * 256];
        const float4* u4 = (const float4*)sh_p[0];
        const float4* v4 = (const float4*)sh_p[1];
        float a0 = 0.f, b0 = 0.f, a1 = 0.f, b1 = 0.f;
        #pragma unroll 8
        for (int k4 = 0; k4 < 64; k4 += 2) {
            {
                const float4 w = wt[k4], u = u4[k4], v = v4[k4];
                a0 = fmaf(w.x, u.x, a0); a0 = fmaf(w.y, u.y, a0);
                a0 = fmaf(w.z, u.z, a0); a0 = fmaf(w.w, u.w, a0);
                a1 = fmaf(w.x, v.x, a1); a1 = fmaf(w.y, v.y, a1);
                a1 = fmaf(w.z, v.z, a1); a1 = fmaf(w.w, v.w, a1);
            }
            {
                const float4 w = wt[k4 + 1], u = u4[k4 + 1], v = v4[k4 + 1];
                b0 = fmaf(w.x, u.x, b0); b0 = fmaf(w.y, u.y, b0);
                b0 = fmaf(w.z, u.z, b0); b0 = fmaf(w.w, u.w, b0);
                b1 = fmaf(w.x, v.x, b1); b1 = fmaf(w.y, v.y, b1);
                b1 = fmaf(w.z, v.z, b1); b1 = fmaf(w.w, v.w, b1);
            }
        }
        const float b = __ldg(&pe_b2[tid]);
        p2[0] = b + a0 + b0; p2[1] = b + a1 + b1;

        float4 s = blockSum4(make_float4(p2[0], p2[1], p2[0]*p2[0], p2[1]*p2[1]), sh_red);
        const float g = __ldg(&pe_g2[tid]), be = __ldg(&pe_be2[tid]);
        {
            float m = s.x * (1.0f / 256.0f);
            float var = s.z * (1.0f / 256.0f) - m * m;
            p2[0] = fmaxf((p2[0] - m) * rsqrtf(var + LN_EPS) * g + be, 0.0f);
        }
        {
            float m = s.y * (1.0f / 256.0f);
            float var = s.w * (1.0f / 256.0f) - m * m;
            p2[1] = fmaxf((p2[1] - m) * rsqrtf(var + LN_EPS) * g + be, 0.0f);
        }
    }

    // ---- h = ov + residual(qe) + pos
    sh_x[0][tid] = ov[0] + qe[0] + p2[0];
    sh_x[1][tid] = ov[1] + qe[1] + p2[1];
    __syncthreads();

    // ---- W_fin GEMV (256 -> 64), transposed, split-k x2.
    //      tid = p*128 + j*64 + c
    {
        const int p = tid >> 7;
        const int j = (tid >> 6) & 1;
        const int c = tid & 63;
        const float4* wt = (const float4*)&g_WfinT[c * 256 + p * 128];
        const float4* x4 = (const float4*)sh_x[j] + p * 32;
        float a = 0.f, b = 0.f;
        #pragma unroll 8
        for (int k4 = 0; k4 < 32; k4 += 2) {
            {
                const float4 w = wt[k4], u = x4[k4];
                a = fmaf(w.x, u.x, a); a = fmaf(w.y, u.y, a);
                a = fmaf(w.z, u.z, a); a = fmaf(w.w, u.w, a);
            }
            {
                const float4 w = wt[k4 + 1], u = x4[k4 + 1];
                b = fmaf(w.x, u.x, b); b = fmaf(w.y, u.y, b);
                b = fmaf(w.z, u.z, b); b = fmaf(w.w, u.w, b);
            }
        }
        sh_part[tid] = a + b;
    }
    __syncthreads();

    // ---- combine halves, LN over 64 channels, write out (threads 0..127)
    float y = 0.0f;
    if (tid < 128) {
        const int c = tid & 63;
        y = __ldg(&b_fin[c]) + sh_part[tid] + sh_part[128 + tid];
        float sx = y, sxx = y * y;
        #pragma unroll
        for (int s = 16; s >= 1; s >>= 1) {
            sx  += __shfl_xor_sync(0xffffffffu, sx,  s);
            sxx += __shfl_xor_sync(0xffffffffu, sxx, s);
        }
        if (lane == 0) sh_fin[warp] = make_float2(sx, sxx);
    }
    __syncthreads();
    if (tid < 128) {
        const int c = tid & 63;
        const int j = tid >> 6;
        float2 a = sh_fin[j * 2];
        float2 b = sh_fin[j * 2 + 1];
        float m   = (a.x + b.x) * (1.0f / 64.0f);
        float var = (a.y + b.y) * (1.0f / 64.0f) - m * m;
        out[(qb + j) * 64 + c] =
            (y - m) * rsqrtf(var + LN_EPS) * __ldg(&g_norm[c]) + __ldg(&b_norm[c]);
    }
}

extern "C" void kernel_launch(void* const* d_in, const int* in_sizes, int n_in,
                              void* d_out, int out_size) {
    (void)in_sizes; (void)n_in; (void)out_size;
    const float* query     = (const float*)d_in[0];
    const float* query_pos = (const float*)d_in[1];
    const float* refp      = (const float*)d_in[2];
    const float* l2i       = (const float*)d_in[3];
    const float* f0        = (const float*)d_in[4];
    const float* f1        = (const float*)d_in[5];
    const float* f2        = (const float*)d_in[6];
    const float* f3        = (const float*)d_in[7];
    const float* W_qe      = (const float*)d_in[8];
    const float* b_qe      = (const float*)d_in[9];
    const float* W_attn    = (const float*)d_in[10];
    const float* b_attn    = (const float*)d_in[11];
    const float* W_out     = (const float*)d_in[12];
    const float* b_out     = (const float*)d_in[13];
    const float* pe_w1     = (const float*)d_in[14];
    const float* pe_b1     = (const float*)d_in[15];
    const float* pe_g1     = (const float*)d_in[16];
    const float* pe_be1    = (const float*)d_in[17];
    const float* pe_w2     = (const float*)d_in[18];
    const float* pe_b2     = (const float*)d_in[19];
    const float* pe_g2     = (const float*)d_in[20];
    const float* pe_be2    = (const float*)d_in[21];
    const float* W_fin     = (const float*)d_in[22];
    const float* b_fin     = (const float*)d_in[23];
    const float* g_norm    = (const float*)d_in[24];
    const float* b_norm    = (const float*)d_in[25];

    transpose_weights<<<256, 256>>>(W_out, pe_w2, W_qe, W_fin);
    detr3d_fused_kernel<<<1024 / QPB, 256>>>(
        query, query_pos, refp, l2i, f0, f1, f2, f3,
        b_qe, W_attn, b_attn, b_out,
        pe_w1, pe_b1, pe_g1, pe_be1, pe_b2, pe_g2, pe_be2,
        b_fin, g_norm, b_norm, (float*)d_out);
}

// round 11
// speedup vs baseline: 2.6700x; 2.6700x over previous
#include <cuda_runtime.h>

#define QPB 2
#define LN_EPS 1e-5f
#define Z_EPS  1e-5f

// k-packed weights: WP[k4*C + c] = {W[(4k4+0)*C+c], ..., W[(4k4+3)*C+c]}
// Lane-adjacent channels stay contiguous -> coalesced LDG.128.
__device__ float4 g_WoutP[64 * 256];
__device__ float4 g_pew2P[64 * 256];
__device__ float4 g_WqeP [16 * 256];
__device__ float4 g_WfinP[64 * 64];

__global__ __launch_bounds__(256)
void pack_weights(const float* __restrict__ Wout, const float* __restrict__ pew2,
                  const float* __restrict__ Wqe,  const float* __restrict__ Wfin) {
    const int idx = blockIdx.x * 256 + threadIdx.x;   // 0 .. 16383
    {
        const int k4 = idx >> 8, c = idx & 255;
        g_WoutP[idx] = make_float4(Wout[(4 * k4 + 0) * 256 + c], Wout[(4 * k4 + 1) * 256 + c],
                                   Wout[(4 * k4 + 2) * 256 + c], Wout[(4 * k4 + 3) * 256 + c]);
        g_pew2P[idx] = make_float4(pew2[(4 * k4 + 0) * 256 + c], pew2[(4 * k4 + 1) * 256 + c],
                                   pew2[(4 * k4 + 2) * 256 + c], pew2[(4 * k4 + 3) * 256 + c]);
    }
    if (idx < 4096) {
        {
            const int k4 = idx >> 8, c = idx & 255;   // 16 x 256
            g_WqeP[idx] = make_float4(Wqe[(4 * k4 + 0) * 256 + c], Wqe[(4 * k4 + 1) * 256 + c],
                                      Wqe[(4 * k4 + 2) * 256 + c], Wqe[(4 * k4 + 3) * 256 + c]);
        }
        {
            const int k4 = idx >> 6, c = idx & 63;    // 64 x 64
            g_WfinP[idx] = make_float4(Wfin[(4 * k4 + 0) * 64 + c], Wfin[(4 * k4 + 1) * 64 + c],
                                       Wfin[(4 * k4 + 2) * 64 + c], Wfin[(4 * k4 + 3) * 64 + c]);
        }
    }
}

// Block-wide sum of a float4 across 256 threads.
__device__ __forceinline__ float4 blockSum4(float4 v, float4* red) {
    const int tid  = threadIdx.x;
    const int lane = tid & 31, warp = tid >> 5;
    #pragma unroll
    for (int s = 16; s >= 1; s >>= 1) {
        v.x += __shfl_xor_sync(0xffffffffu, v.x, s);
        v.y += __shfl_xor_sync(0xffffffffu, v.y, s);
        v.z += __shfl_xor_sync(0xffffffffu, v.z, s);
        v.w += __shfl_xor_sync(0xffffffffu, v.w, s);
    }
    if (lane == 0) red[warp] = v;
    __syncthreads();
    if (warp == 0) {
        float4 t = (lane < 8) ? red[lane] : make_float4(0.f, 0.f, 0.f, 0.f);
        #pragma unroll
        for (int s = 4; s >= 1; s >>= 1) {
            t.x += __shfl_xor_sync(0xffffffffu, t.x, s);
            t.y += __shfl_xor_sync(0xffffffffu, t.y, s);
            t.z += __shfl_xor_sync(0xffffffffu, t.z, s);
            t.w += __shfl_xor_sync(0xffffffffu, t.w, s);
        }
        if (lane == 0) red[0] = t;
    }
    __syncthreads();
    float4 r = red[0];
    __syncthreads();
    return r;
}

__global__ __launch_bounds__(256)
void detr3d_fused_kernel(
    const float* __restrict__ query, const float* __restrict__ query_pos,
    const float* __restrict__ refp,  const float* __restrict__ l2i,
    const float* __restrict__ f0, const float* __restrict__ f1,
    const float* __restrict__ f2, const float* __restrict__ f3,
    const float* __restrict__ b_qe,
    const float* __restrict__ W_attn, const float* __restrict__ b_attn,
    const float* __restrict__ b_out,
    const float* __restrict__ pe_w1,  const float* __restrict__ pe_b1,
    const float* __restrict__ pe_g1,  const float* __restrict__ pe_be1,
    const float* __restrict__ pe_b2,
    const float* __restrict__ pe_g2,  const float* __restrict__ pe_be2,
    const float* __restrict__ b_fin,
    const float* __restrict__ g_norm, const float* __restrict__ b_norm,
    float* __restrict__ out)
{
    const int qb   = blockIdx.x * QPB;
    const int tid  = threadIdx.x;
    const int lane = tid & 31, warp = tid >> 5;

    __shared__ __align__(16) float sh_q[QPB][64];
    __shared__ float  sh_ref[QPB][3];
    __shared__ float  sh_qe[QPB][256];
    __shared__ __align__(16) float sh_x[QPB][256];  // gather acc; later h
    __shared__ __align__(16) float sh_p[QPB][256];  // pos MLP hidden
    __shared__ float  sh_part[256];                 // W_fin partials
    __shared__ float4 sh_red[8];
    __shared__ float2 sh_fin[4];
    __shared__ float  sh_w[QPB][24];
    __shared__ int4   sh_gi[QPB][6][4];
    __shared__ float4 sh_gw[QPB][6][4];
    __shared__ int    sh_mask[QPB][6];

    // ---- load q = query + query_pos, reference points
    if (tid < QPB * 64) {
        const int j = tid >> 6, c = tid & 63;
        sh_q[j][c] = query[(qb + j) * 64 + c] + query_pos[(qb + j) * 64 + c];
    }
    if (tid >= 128 && tid < 128 + QPB * 3) {
        const int i = tid - 128;
        sh_ref[i / 3][i % 3] = refp[(qb + i / 3) * 3 + i % 3];
    }
    __syncthreads();

    // ---- qe GEMV (64 -> 256), k-packed weights; thread = channel
    float qe[QPB];
    {
        const float4* u4 = (const float4*)sh_q[0];
        const float4* v4 = (const float4*)sh_q[1];
        float a0 = 0.f, b0 = 0.f, a1 = 0.f, b1 = 0.f;
        #pragma unroll
        for (int k4 = 0; k4 < 16; k4++) {
            const float4 w = g_WqeP[k4 * 256 + tid];
            const float4 u = u4[k4];
            const float4 v = v4[k4];
            a0 = fmaf(w.x, u.x, fmaf(w.y, u.y, a0));
            b0 = fmaf(w.z, u.z, fmaf(w.w, u.w, b0));
            a1 = fmaf(w.x, v.x, fmaf(w.y, v.y, a1));
            b1 = fmaf(w.z, v.z, fmaf(w.w, v.w, b1));
        }
        const float b = __ldg(&b_qe[tid]);
        qe[0] = b + a0 + b0; qe[1] = b + a1 + b1;
        sh_qe[0][tid] = qe[0]; sh_qe[1][tid] = qe[1];
    }

    // ---- projection + tap precompute (threads 0..47; 1 per (j,n,l))
    if (tid < QPB * 24) {
        const int j = tid / 24, r = tid % 24, n = r / 4, l = r % 4;
        const int Hs[4] = { 116, 58, 29, 15 };
        const int Ws[4] = { 200, 100, 50, 25 };
        const float* M = l2i + n * 16;
        const float rx = sh_ref[j][0], ry = sh_ref[j][1], rz = sh_ref[j][2];
        float c0 = M[0] * rx + M[1] * ry + M[2]  * rz + M[3];
        float c1 = M[4] * rx + M[5] * ry + M[6]  * rz + M[7];
        float c2 = M[8] * rx + M[9] * ry + M[10] * rz + M[11];
        bool front = c2 > Z_EPS;
        float zc = fmaxf(c2, Z_EPS);
        float gx = (c0 / zc / 1600.0f - 0.5f) * 2.0f;
        float gy = (c1 / zc / 928.0f  - 0.5f) * 2.0f;
        bool inb = (gx > -1.0f) && (gx < 1.0f) && (gy > -1.0f) && (gy < 1.0f);
        if (l == 0) sh_mask[j][n] = (front && inb) ? 1 : 0;

        const int W = Ws[l], H = Hs[l];
        float x = ((gx + 1.0f) * (float)W - 1.0f) * 0.5f;
        float y = ((gy + 1.0f) * (float)H - 1.0f) * 0.5f;
        float fx0 = floorf(x), fy0 = floorf(y);
        int x0 = (int)fx0, y0 = (int)fy0;
        float wx1 = x - fx0, wx0 = 1.0f - wx1;
        float wy1 = y - fy0, wy0 = 1.0f - wy1;
        float vx0 = (x0 >= 0 && x0 < W) ? 1.0f : 0.0f;
        float vx1 = (x0 + 1 >= 0 && x0 + 1 < W) ? 1.0f : 0.0f;
        float vy0 = (y0 >= 0 && y0 < H) ? 1.0f : 0.0f;
        float vy1 = (y0 + 1 >= 0 && y0 + 1 < H) ? 1.0f : 0.0f;
        int cx0 = min(max(x0, 0), W - 1);
        int cx1 = min(max(x0 + 1, 0), W - 1);
        int cy0 = min(max(y0, 0), H - 1);
        int cy1 = min(max(y0 + 1, 0), H - 1);
        sh_gi[j][n][l] = make_int4(cy0 * W + cx0, cy0 * W + cx1,
                                   cy1 * W + cx0, cy1 * W + cx1);
        sh_gw[j][n][l] = make_float4(wy0 * wx0 * vy0 * vx0, wy0 * wx1 * vy0 * vx1,
                                     wy1 * wx0 * vy1 * vx0, wy1 * wx1 * vy1 * vx1);
    }
    __syncthreads();

    // ---- attw: warp-split GEMV; warp w owns outputs {w, w+8, w+16}
    {
        float acc[3][QPB];
        #pragma unroll
        for (int i = 0; i < 3; i++)
            #pragma unroll
            for (int j = 0; j < QPB; j++) acc[i][j] = 0.0f;
        #pragma unroll
        for (int kk = 0; kk < 8; kk++) {
            const int k = lane + 32 * kk;
            const float q0 = sh_qe[0][k];
            const float q1 = sh_qe[1][k];
            #pragma unroll
            for (int i = 0; i < 3; i++) {
                const float wv = __ldg(&W_attn[k * 24 + warp + 8 * i]);
                acc[i][0] = fmaf(q0, wv, acc[i][0]);
                acc[i][1] = fmaf(q1, wv, acc[i][1]);
            }
        }
        #pragma unroll
        for (int i = 0; i < 3; i++)
            #pragma unroll
            for (int j = 0; j < QPB; j++) {
                #pragma unroll
                for (int s = 16; s >= 1; s >>= 1)
                    acc[i][j] += __shfl_xor_sync(0xffffffffu, acc[i][j], s);
            }
        if (lane == 0) {
            #pragma unroll
            for (int i = 0; i < 3; i++) {
                const int o = warp + 8 * i;
                const float b = __ldg(&b_attn[o]);
                sh_w[0][o] = 1.0f / (1.0f + expf(-(acc[i][0] + b)));
                sh_w[1][o] = 1.0f / (1.0f + expf(-(acc[i][1] + b)));
            }
        }
    }
    __syncthreads();

    // ---- masked bilinear gather (precomputed taps). thread = channel.
    {
        const float* fps[4] = { f0, f1, f2, f3 };
        const int HWs[4] = { 116 * 200, 58 * 100, 29 * 50, 15 * 25 };
        float acc[QPB];
        #pragma unroll
        for (int j = 0; j < QPB; j++) acc[j] = 0.0f;
        #pragma unroll
        for (int j = 0; j < QPB; j++) {
            for (int n = 0; n < 6; n++) {
                if (!sh_mask[j][n]) continue;
                #pragma unroll
                for (int l = 0; l < 4; l++) {
                    const int4   o = sh_gi[j][n][l];
                    const float4 w = sh_gw[j][n][l];
                    const float* fb = fps[l] + (size_t)(n * 256 + tid) * (size_t)HWs[l];
                    float v = w.x * __ldg(fb + o.x)
                            + w.y * __ldg(fb + o.y)
                            + w.z * __ldg(fb + o.z)
                            + w.w * __ldg(fb + o.w);
                    acc[j] = fmaf(sh_w[j][n * 4 + l], v, acc[j]);
                }
            }
        }
        sh_x[0][tid] = acc[0]; sh_x[1][tid] = acc[1];
    }
    __syncthreads();

    // ---- W_out GEMV (256 -> 256), k-packed, coalesced; thread = channel
    float ov[QPB];
    {
        const float4* u4 = (const float4*)sh_x[0];
        const float4* v4 = (const float4*)sh_x[1];
        float a0 = 0.f, b0 = 0.f, a1 = 0.f, b1 = 0.f;
        #pragma unroll 8
        for (int k4 = 0; k4 < 64; k4++) {
            const float4 w = g_WoutP[k4 * 256 + tid];
            const float4 u = u4[k4];
            const float4 v = v4[k4];
            a0 = fmaf(w.x, u.x, fmaf(w.y, u.y, a0));
            b0 = fmaf(w.z, u.z, fmaf(w.w, u.w, b0));
            a1 = fmaf(w.x, v.x, fmaf(w.y, v.y, a1));
            b1 = fmaf(w.z, v.z, fmaf(w.w, v.w, b1));
        }
        const float b = __ldg(&b_out[tid]);
        ov[0] = b + a0 + b0; ov[1] = b + a1 + b1;
    }

    // ---- positional MLP stage 1: ref @ pe_w1 + pe_b1 -> LN -> relu
    {
        const float w1 = __ldg(&pe_w1[tid]);
        const float w2 = __ldg(&pe_w1[256 + tid]);
        const float w3 = __ldg(&pe_w1[512 + tid]);
        const float b  = __ldg(&pe_b1[tid]);
        float p[QPB];
        #pragma unroll
        for (int j = 0; j < QPB; j++)
            p[j] = b + sh_ref[j][0] * w1 + sh_ref[j][1] * w2 + sh_ref[j][2] * w3;
        float4 s = blockSum4(make_float4(p[0], p[1], p[0]*p[0], p[1]*p[1]), sh_red);
        const float g = __ldg(&pe_g1[tid]), be = __ldg(&pe_be1[tid]);
        {
            float m = s.x * (1.0f / 256.0f);
            float var = s.z * (1.0f / 256.0f) - m * m;
            sh_p[0][tid] = fmaxf((p[0] - m) * rsqrtf(var + LN_EPS) * g + be, 0.0f);
        }
        {
            float m = s.y * (1.0f / 256.0f);
            float var = s.w * (1.0f / 256.0f) - m * m;
            sh_p[1][tid] = fmaxf((p[1] - m) * rsqrtf(var + LN_EPS) * g + be, 0.0f);
        }
    }
    __syncthreads();

    // ---- pe_w2 GEMV (256 -> 256), k-packed, coalesced
    float p2[QPB];
    {
        const float4* u4 = (const float4*)sh_p[0];
        const float4* v4 = (const float4*)sh_p[1];
        float a0 = 0.f, b0 = 0.f, a1 = 0.f, b1 = 0.f;
        #pragma unroll 8
        for (int k4 = 0; k4 < 64; k4++) {
            const float4 w = g_pew2P[k4 * 256 + tid];
            const float4 u = u4[k4];
            const float4 v = v4[k4];
            a0 = fmaf(w.x, u.x, fmaf(w.y, u.y, a0));
            b0 = fmaf(w.z, u.z, fmaf(w.w, u.w, b0));
            a1 = fmaf(w.x, v.x, fmaf(w.y, v.y, a1));
            b1 = fmaf(w.z, v.z, fmaf(w.w, v.w, b1));
        }
        const float b = __ldg(&pe_b2[tid]);
        p2[0] = b + a0 + b0; p2[1] = b + a1 + b1;

        float4 s = blockSum4(make_float4(p2[0], p2[1], p2[0]*p2[0], p2[1]*p2[1]), sh_red);
        const float g = __ldg(&pe_g2[tid]), be = __ldg(&pe_be2[tid]);
        {
            float m = s.x * (1.0f / 256.0f);
            float var = s.z * (1.0f / 256.0f) - m * m;
            p2[0] = fmaxf((p2[0] - m) * rsqrtf(var + LN_EPS) * g + be, 0.0f);
        }
        {
            float m = s.y * (1.0f / 256.0f);
            float var = s.w * (1.0f / 256.0f) - m * m;
            p2[1] = fmaxf((p2[1] - m) * rsqrtf(var + LN_EPS) * g + be, 0.0f);
        }
    }

    // ---- h = ov + residual(qe) + pos
    sh_x[0][tid] = ov[0] + qe[0] + p2[0];
    sh_x[1][tid] = ov[1] + qe[1] + p2[1];
    __syncthreads();

    // ---- W_fin GEMV (256 -> 64), k-packed, split-k x2. tid = p*128 + j*64 + c
    {
        const int p = tid >> 7;
        const int j = (tid >> 6) & 1;
        const int c = tid & 63;
        const float4* x4 = (const float4*)sh_x[j] + p * 32;
        const float4* wp = &g_WfinP[p * 32 * 64];
        float a = 0.f, b = 0.f;
        #pragma unroll 8
        for (int k4 = 0; k4 < 32; k4++) {
            const float4 w = wp[k4 * 64 + c];
            const float4 u = x4[k4];
            a = fmaf(w.x, u.x, fmaf(w.y, u.y, a));
            b = fmaf(w.z, u.z, fmaf(w.w, u.w, b));
        }
        sh_part[tid] = a + b;
    }
    __syncthreads();

    // ---- combine halves, LN over 64 channels, write out (threads 0..127)
    float y = 0.0f;
    if (tid < 128) {
        const int c = tid & 63;
        y = __ldg(&b_fin[c]) + sh_part[tid] + sh_part[128 + tid];
        float sx = y, sxx = y * y;
        #pragma unroll
        for (int s = 16; s >= 1; s >>= 1) {
            sx  += __shfl_xor_sync(0xffffffffu, sx,  s);
            sxx += __shfl_xor_sync(0xffffffffu, sxx, s);
        }
        if (lane == 0) sh_fin[warp] = make_float2(sx, sxx);
    }
    __syncthreads();
    if (tid < 128) {
        const int c = tid & 63;
        const int j = tid >> 6;
        float2 a = sh_fin[j * 2];
        float2 b = sh_fin[j * 2 + 1];
        float m   = (a.x + b.x) * (1.0f / 64.0f);
        float var = (a.y + b.y) * (1.0f / 64.0f) - m * m;
        out[(qb + j) * 64 + c] =
            (y - m) * rsqrtf(var + LN_EPS) * __ldg(&g_norm[c]) + __ldg(&b_norm[c]);
    }
}

extern "C" void kernel_launch(void* const* d_in, const int* in_sizes, int n_in,
                              void* d_out, int out_size) {
    (void)in_sizes; (void)n_in; (void)out_size;
    const float* query     = (const float*)d_in[0];
    const float* query_pos = (const float*)d_in[1];
    const float* refp      = (const float*)d_in[2];
    const float* l2i       = (const float*)d_in[3];
    const float* f0        = (const float*)d_in[4];
    const float* f1        = (const float*)d_in[5];
    const float* f2        = (const float*)d_in[6];
    const float* f3        = (const float*)d_in[7];
    const float* W_qe      = (const float*)d_in[8];
    const float* b_qe      = (const float*)d_in[9];
    const float* W_attn    = (const float*)d_in[10];
    const float* b_attn    = (const float*)d_in[11];
    const float* W_out     = (const float*)d_in[12];
    const float* b_out     = (const float*)d_in[13];
    const float* pe_w1     = (const float*)d_in[14];
    const float* pe_b1     = (const float*)d_in[15];
    const float* pe_g1     = (const float*)d_in[16];
    const float* pe_be1    = (const float*)d_in[17];
    const float* pe_w2     = (const float*)d_in[18];
    const float* pe_b2     = (const float*)d_in[19];
    const float* pe_g2     = (const float*)d_in[20];
    const float* pe_be2    = (const float*)d_in[21];
    const float* W_fin     = (const float*)d_in[22];
    const float* b_fin     = (const float*)d_in[23];
    const float* g_norm    = (const float*)d_in[24];
    const float* b_norm    = (const float*)d_in[25];

    pack_weights<<<64, 256>>>(W_out, pe_w2, W_qe, W_fin);
    detr3d_fused_kernel<<<1024 / QPB, 256>>>(
        query, query_pos, refp, l2i, f0, f1, f2, f3,
        b_qe, W_attn, b_attn, b_out,
        pe_w1, pe_b1, pe_g1, pe_be1, pe_b2, pe_g2, pe_be2,
        b_fin, g_norm, b_norm, (float*)d_out);
}

// round 12
// speedup vs baseline: 2.6990x; 1.0109x over previous
#include <cuda_runtime.h>

#define QPB 2
#define LN_EPS 1e-5f
#define Z_EPS  1e-5f

// k-packed weights: WP[k4*C + c] = {W[(4k4+0)*C+c], ..., W[(4k4+3)*C+c]}
__device__ float4 g_WoutP[64 * 256];
__device__ float4 g_pew2P[64 * 256];
__device__ float4 g_WqeP [16 * 256];
__device__ float4 g_WfinP[64 * 64];

__global__ __launch_bounds__(256)
void pack_weights(const float* __restrict__ Wout, const float* __restrict__ pew2,
                  const float* __restrict__ Wqe,  const float* __restrict__ Wfin) {
    const int bid = blockIdx.x;
    if (bid < 64) {
        const int idx = bid * 256 + threadIdx.x;       // 0 .. 16383
        const int k4 = idx >> 8, c = idx & 255;
        g_WoutP[idx] = make_float4(Wout[(4 * k4 + 0) * 256 + c], Wout[(4 * k4 + 1) * 256 + c],
                                   Wout[(4 * k4 + 2) * 256 + c], Wout[(4 * k4 + 3) * 256 + c]);
        g_pew2P[idx] = make_float4(pew2[(4 * k4 + 0) * 256 + c], pew2[(4 * k4 + 1) * 256 + c],
                                   pew2[(4 * k4 + 2) * 256 + c], pew2[(4 * k4 + 3) * 256 + c]);
    } else {
        const int idx = (bid - 64) * 256 + threadIdx.x; // 0 .. 4095
        {
            const int k4 = idx >> 8, c = idx & 255;     // 16 x 256
            g_WqeP[idx] = make_float4(Wqe[(4 * k4 + 0) * 256 + c], Wqe[(4 * k4 + 1) * 256 + c],
                                      Wqe[(4 * k4 + 2) * 256 + c], Wqe[(4 * k4 + 3) * 256 + c]);
        }
        {
            const int k4 = idx >> 6, c = idx & 63;      // 64 x 64
            g_WfinP[idx] = make_float4(Wfin[(4 * k4 + 0) * 64 + c], Wfin[(4 * k4 + 1) * 64 + c],
                                       Wfin[(4 * k4 + 2) * 64 + c], Wfin[(4 * k4 + 3) * 64 + c]);
        }
    }
}

// Block-wide sum of a float4 across 256 threads.
__device__ __forceinline__ float4 blockSum4(float4 v, float4* red) {
    const int tid  = threadIdx.x;
    const int lane = tid & 31, warp = tid >> 5;
    #pragma unroll
    for (int s = 16; s >= 1; s >>= 1) {
        v.x += __shfl_xor_sync(0xffffffffu, v.x, s);
        v.y += __shfl_xor_sync(0xffffffffu, v.y, s);
        v.z += __shfl_xor_sync(0xffffffffu, v.z, s);
        v.w += __shfl_xor_sync(0xffffffffu, v.w, s);
    }
    if (lane == 0) red[warp] = v;
    __syncthreads();
    if (warp == 0) {
        float4 t = (lane < 8) ? red[lane] : make_float4(0.f, 0.f, 0.f, 0.f);
        #pragma unroll
        for (int s = 4; s >= 1; s >>= 1) {
            t.x += __shfl_xor_sync(0xffffffffu, t.x, s);
            t.y += __shfl_xor_sync(0xffffffffu, t.y, s);
            t.z += __shfl_xor_sync(0xffffffffu, t.z, s);
            t.w += __shfl_xor_sync(0xffffffffu, t.w, s);
        }
        if (lane == 0) red[0] = t;
    }
    __syncthreads();
    float4 r = red[0];
    __syncthreads();
    return r;
}

__global__ __launch_bounds__(256)
void detr3d_fused_kernel(
    const float* __restrict__ query, const float* __restrict__ query_pos,
    const float* __restrict__ refp,  const float* __restrict__ l2i,
    const float* __restrict__ f0, const float* __restrict__ f1,
    const float* __restrict__ f2, const float* __restrict__ f3,
    const float* __restrict__ b_qe,
    const float* __restrict__ W_attn, const float* __restrict__ b_attn,
    const float* __restrict__ b_out,
    const float* __restrict__ pe_w1,  const float* __restrict__ pe_b1,
    const float* __restrict__ pe_g1,  const float* __restrict__ pe_be1,
    const float* __restrict__ pe_b2,
    const float* __restrict__ pe_g2,  const float* __restrict__ pe_be2,
    const float* __restrict__ b_fin,
    const float* __restrict__ g_norm, const float* __restrict__ b_norm,
    float* __restrict__ out)
{
    const int qb   = blockIdx.x * QPB;
    const int tid  = threadIdx.x;
    const int lane = tid & 31, warp = tid >> 5;

    __shared__ __align__(16) float sh_q[QPB][64];
    __shared__ float  sh_ref[QPB][3];
    __shared__ float  sh_qe[QPB][256];
    __shared__ __align__(16) float sh_x[QPB][256];  // gather acc; later h
    __shared__ __align__(16) float sh_p[QPB][256];  // pos MLP hidden
    __shared__ float  sh_part[256];                 // W_fin partials
    __shared__ float4 sh_red[8];
    __shared__ float2 sh_fin[4];
    __shared__ float  sh_w[QPB][24];
    __shared__ int4   sh_gi[QPB][6][4];
    __shared__ float4 sh_gw[QPB][6][4];
    __shared__ int    sh_mask[QPB][6];

    // ---- load q = query + query_pos, reference points
    if (tid < QPB * 64) {
        const int j = tid >> 6, c = tid & 63;
        sh_q[j][c] = query[(qb + j) * 64 + c] + query_pos[(qb + j) * 64 + c];
    }
    if (tid >= 128 && tid < 128 + QPB * 3) {
        const int i = tid - 128;
        sh_ref[i / 3][i % 3] = refp[(qb + i / 3) * 3 + i % 3];
    }
    __syncthreads();

    // ---- qe GEMV (64 -> 256), k-packed weights; thread = channel
    float qe[QPB];
    {
        const float4* u4 = (const float4*)sh_q[0];
        const float4* v4 = (const float4*)sh_q[1];
        float a0 = 0.f, b0 = 0.f, a1 = 0.f, b1 = 0.f;
        #pragma unroll
        for (int k4 = 0; k4 < 16; k4++) {
            const float4 w = g_WqeP[k4 * 256 + tid];
            const float4 u = u4[k4];
            const float4 v = v4[k4];
            a0 = fmaf(w.x, u.x, fmaf(w.y, u.y, a0));
            b0 = fmaf(w.z, u.z, fmaf(w.w, u.w, b0));
            a1 = fmaf(w.x, v.x, fmaf(w.y, v.y, a1));
            b1 = fmaf(w.z, v.z, fmaf(w.w, v.w, b1));
        }
        const float b = __ldg(&b_qe[tid]);
        qe[0] = b + a0 + b0; qe[1] = b + a1 + b1;
        sh_qe[0][tid] = qe[0]; sh_qe[1][tid] = qe[1];
    }

    // ---- projection + tap precompute (threads 0..47; 1 per (j,n,l))
    if (tid < QPB * 24) {
        const int j = tid / 24, r = tid % 24, n = r / 4, l = r % 4;
        const int Hs[4] = { 116, 58, 29, 15 };
        const int Ws[4] = { 200, 100, 50, 25 };
        const float* M = l2i + n * 16;
        const float rx = sh_ref[j][0], ry = sh_ref[j][1], rz = sh_ref[j][2];
        float c0 = M[0] * rx + M[1] * ry + M[2]  * rz + M[3];
        float c1 = M[4] * rx + M[5] * ry + M[6]  * rz + M[7];
        float c2 = M[8] * rx + M[9] * ry + M[10] * rz + M[11];
        bool front = c2 > Z_EPS;
        float zc = fmaxf(c2, Z_EPS);
        float gx = (c0 / zc / 1600.0f - 0.5f) * 2.0f;
        float gy = (c1 / zc / 928.0f  - 0.5f) * 2.0f;
        bool inb = (gx > -1.0f) && (gx < 1.0f) && (gy > -1.0f) && (gy < 1.0f);
        if (l == 0) sh_mask[j][n] = (front && inb) ? 1 : 0;

        const int W = Ws[l], H = Hs[l];
        float x = ((gx + 1.0f) * (float)W - 1.0f) * 0.5f;
        float y = ((gy + 1.0f) * (float)H - 1.0f) * 0.5f;
        float fx0 = floorf(x), fy0 = floorf(y);
        int x0 = (int)fx0, y0 = (int)fy0;
        float wx1 = x - fx0, wx0 = 1.0f - wx1;
        float wy1 = y - fy0, wy0 = 1.0f - wy1;
        float vx0 = (x0 >= 0 && x0 < W) ? 1.0f : 0.0f;
        float vx1 = (x0 + 1 >= 0 && x0 + 1 < W) ? 1.0f : 0.0f;
        float vy0 = (y0 >= 0 && y0 < H) ? 1.0f : 0.0f;
        float vy1 = (y0 + 1 >= 0 && y0 + 1 < H) ? 1.0f : 0.0f;
        int cx0 = min(max(x0, 0), W - 1);
        int cx1 = min(max(x0 + 1, 0), W - 1);
        int cy0 = min(max(y0, 0), H - 1);
        int cy1 = min(max(y0 + 1, 0), H - 1);
        sh_gi[j][n][l] = make_int4(cy0 * W + cx0, cy0 * W + cx1,
                                   cy1 * W + cx0, cy1 * W + cx1);
        sh_gw[j][n][l] = make_float4(wy0 * wx0 * vy0 * vx0, wy0 * wx1 * vy0 * vx1,
                                     wy1 * wx0 * vy1 * vx0, wy1 * wx1 * vy1 * vx1);
    }
    __syncthreads();

    // ---- attw: warp-split GEMV; warp w owns outputs {w, w+8, w+16}
    {
        float acc[3][QPB];
        #pragma unroll
        for (int i = 0; i < 3; i++)
            #pragma unroll
            for (int j = 0; j < QPB; j++) acc[i][j] = 0.0f;
        #pragma unroll
        for (int kk = 0; kk < 8; kk++) {
            const int k = lane + 32 * kk;
            const float q0 = sh_qe[0][k];
            const float q1 = sh_qe[1][k];
            #pragma unroll
            for (int i = 0; i < 3; i++) {
                const float wv = __ldg(&W_attn[k * 24 + warp + 8 * i]);
                acc[i][0] = fmaf(q0, wv, acc[i][0]);
                acc[i][1] = fmaf(q1, wv, acc[i][1]);
            }
        }
        #pragma unroll
        for (int i = 0; i < 3; i++)
            #pragma unroll
            for (int j = 0; j < QPB; j++) {
                #pragma unroll
                for (int s = 16; s >= 1; s >>= 1)
                    acc[i][j] += __shfl_xor_sync(0xffffffffu, acc[i][j], s);
            }
        if (lane == 0) {
            #pragma unroll
            for (int i = 0; i < 3; i++) {
                const int o = warp + 8 * i;
                const float b = __ldg(&b_attn[o]);
                sh_w[0][o] = 1.0f / (1.0f + expf(-(acc[i][0] + b)));
                sh_w[1][o] = 1.0f / (1.0f + expf(-(acc[i][1] + b)));
            }
        }
    }
    __syncthreads();

    // ---- prefetch first 8 W_out chunks (independent of gather)
    float4 pw[8];
    #pragma unroll
    for (int i = 0; i < 8; i++) pw[i] = g_WoutP[i * 256 + tid];

    // ---- masked bilinear gather (precomputed taps). thread = channel.
    {
        const float* fps[4] = { f0, f1, f2, f3 };
        const int HWs[4] = { 116 * 200, 58 * 100, 29 * 50, 15 * 25 };
        float acc[QPB];
        #pragma unroll
        for (int j = 0; j < QPB; j++) acc[j] = 0.0f;
        #pragma unroll
        for (int j = 0; j < QPB; j++) {
            for (int n = 0; n < 6; n++) {
                if (!sh_mask[j][n]) continue;
                #pragma unroll
                for (int l = 0; l < 4; l++) {
                    const int4   o = sh_gi[j][n][l];
                    const float4 w = sh_gw[j][n][l];
                    const float* fb = fps[l] + (size_t)(n * 256 + tid) * (size_t)HWs[l];
                    float v = w.x * __ldg(fb + o.x)
                            + w.y * __ldg(fb + o.y)
                            + w.z * __ldg(fb + o.z)
                            + w.w * __ldg(fb + o.w);
                    acc[j] = fmaf(sh_w[j][n * 4 + l], v, acc[j]);
                }
            }
        }
        sh_x[0][tid] = acc[0]; sh_x[1][tid] = acc[1];
    }
    __syncthreads();

    // ---- W_out GEMV (256 -> 256), k-packed; first 8 chunks from prefetch
    float ov[QPB];
    {
        const float4* u4 = (const float4*)sh_x[0];
        const float4* v4 = (const float4*)sh_x[1];
        float a0 = 0.f, b0 = 0.f, a1 = 0.f, b1 = 0.f;
        #pragma unroll
        for (int k4 = 0; k4 < 8; k4++) {
            const float4 w = pw[k4];
            const float4 u = u4[k4];
            const float4 v = v4[k4];
            a0 = fmaf(w.x, u.x, fmaf(w.y, u.y, a0));
            b0 = fmaf(w.z, u.z, fmaf(w.w, u.w, b0));
            a1 = fmaf(w.x, v.x, fmaf(w.y, v.y, a1));
            b1 = fmaf(w.z, v.z, fmaf(w.w, v.w, b1));
        }
        #pragma unroll 8
        for (int k4 = 8; k4 < 64; k4++) {
            const float4 w = g_WoutP[k4 * 256 + tid];
            const float4 u = u4[k4];
            const float4 v = v4[k4];
            a0 = fmaf(w.x, u.x, fmaf(w.y, u.y, a0));
            b0 = fmaf(w.z, u.z, fmaf(w.w, u.w, b0));
            a1 = fmaf(w.x, v.x, fmaf(w.y, v.y, a1));
            b1 = fmaf(w.z, v.z, fmaf(w.w, v.w, b1));
        }
        const float b = __ldg(&b_out[tid]);
        ov[0] = b + a0 + b0; ov[1] = b + a1 + b1;
    }

    // ---- positional MLP stage 1: ref @ pe_w1 + pe_b1 -> LN -> relu
    {
        const float w1 = __ldg(&pe_w1[tid]);
        const float w2 = __ldg(&pe_w1[256 + tid]);
        const float w3 = __ldg(&pe_w1[512 + tid]);
        const float b  = __ldg(&pe_b1[tid]);
        float p[QPB];
        #pragma unroll
        for (int j = 0; j < QPB; j++)
            p[j] = b + sh_ref[j][0] * w1 + sh_ref[j][1] * w2 + sh_ref[j][2] * w3;
        float4 s = blockSum4(make_float4(p[0], p[1], p[0]*p[0], p[1]*p[1]), sh_red);
        const float g = __ldg(&pe_g1[tid]), be = __ldg(&pe_be1[tid]);
        {
            float m = s.x * (1.0f / 256.0f);
            float var = s.z * (1.0f / 256.0f) - m * m;
            sh_p[0][tid] = fmaxf((p[0] - m) * rsqrtf(var + LN_EPS) * g + be, 0.0f);
        }
        {
            float m = s.y * (1.0f / 256.0f);
            float var = s.w * (1.0f / 256.0f) - m * m;
            sh_p[1][tid] = fmaxf((p[1] - m) * rsqrtf(var + LN_EPS) * g + be, 0.0f);
        }
    }
    __syncthreads();

    // ---- pe_w2 GEMV (256 -> 256), k-packed, coalesced
    float p2[QPB];
    {
        const float4* u4 = (const float4*)sh_p[0];
        const float4* v4 = (const float4*)sh_p[1];
        float a0 = 0.f, b0 = 0.f, a1 = 0.f, b1 = 0.f;
        #pragma unroll 16
        for (int k4 = 0; k4 < 64; k4++) {
            const float4 w = g_pew2P[k4 * 256 + tid];
            const float4 u = u4[k4];
            const float4 v = v4[k4];
            a0 = fmaf(w.x, u.x, fmaf(w.y, u.y, a0));
            b0 = fmaf(w.z, u.z, fmaf(w.w, u.w, b0));
            a1 = fmaf(w.x, v.x, fmaf(w.y, v.y, a1));
            b1 = fmaf(w.z, v.z, fmaf(w.w, v.w, b1));
        }
        const float b = __ldg(&pe_b2[tid]);
        p2[0] = b + a0 + b0; p2[1] = b + a1 + b1;

        float4 s = blockSum4(make_float4(p2[0], p2[1], p2[0]*p2[0], p2[1]*p2[1]), sh_red);
        const float g = __ldg(&pe_g2[tid]), be = __ldg(&pe_be2[tid]);
        {
            float m = s.x * (1.0f / 256.0f);
            float var = s.z * (1.0f / 256.0f) - m * m;
            p2[0] = fmaxf((p2[0] - m) * rsqrtf(var + LN_EPS) * g + be, 0.0f);
        }
        {
            float m = s.y * (1.0f / 256.0f);
            float var = s.w * (1.0f / 256.0f) - m * m;
            p2[1] = fmaxf((p2[1] - m) * rsqrtf(var + LN_EPS) * g + be, 0.0f);
        }
    }

    // ---- h = ov + residual(qe) + pos
    sh_x[0][tid] = ov[0] + qe[0] + p2[0];
    sh_x[1][tid] = ov[1] + qe[1] + p2[1];
    __syncthreads();

    // ---- W_fin GEMV (256 -> 64), k-packed, split-k x2. tid = p*128 + j*64 + c
    {
        const int p = tid >> 7;
        const int j = (tid >> 6) & 1;
        const int c = tid & 63;
        const float4* x4 = (const float4*)sh_x[j] + p * 32;
        const float4* wp = &g_WfinP[p * 32 * 64];
        float a = 0.f, b = 0.f;
        #pragma unroll 8
        for (int k4 = 0; k4 < 32; k4++) {
            const float4 w = wp[k4 * 64 + c];
            const float4 u = x4[k4];
            a = fmaf(w.x, u.x, fmaf(w.y, u.y, a));
            b = fmaf(w.z, u.z, fmaf(w.w, u.w, b));
        }
        sh_part[tid] = a + b;
    }
    __syncthreads();

    // ---- combine halves, LN over 64 channels, write out (threads 0..127)
    float y = 0.0f;
    if (tid < 128) {
        const int c = tid & 63;
        y = __ldg(&b_fin[c]) + sh_part[tid] + sh_part[128 + tid];
        float sx = y, sxx = y * y;
        #pragma unroll
        for (int s = 16; s >= 1; s >>= 1) {
            sx  += __shfl_xor_sync(0xffffffffu, sx,  s);
            sxx += __shfl_xor_sync(0xffffffffu, sxx, s);
        }
        if (lane == 0) sh_fin[warp] = make_float2(sx, sxx);
    }
    __syncthreads();
    if (tid < 128) {
        const int c = tid & 63;
        const int j = tid >> 6;
        float2 a = sh_fin[j * 2];
        float2 b = sh_fin[j * 2 + 1];
        float m   = (a.x + b.x) * (1.0f / 64.0f);
        float var = (a.y + b.y) * (1.0f / 64.0f) - m * m;
        out[(qb + j) * 64 + c] =
            (y - m) * rsqrtf(var + LN_EPS) * __ldg(&g_norm[c]) + __ldg(&b_norm[c]);
    }
}

extern "C" void kernel_launch(void* const* d_in, const int* in_sizes, int n_in,
                              void* d_out, int out_size) {
    (void)in_sizes; (void)n_in; (void)out_size;
    const float* query     = (const float*)d_in[0];
    const float* query_pos = (const float*)d_in[1];
    const float* refp      = (const float*)d_in[2];
    const float* l2i       = (const float*)d_in[3];
    const float* f0        = (const float*)d_in[4];
    const float* f1        = (const float*)d_in[5];
    const float* f2        = (const float*)d_in[6];
    const float* f3        = (const float*)d_in[7];
    const float* W_qe      = (const float*)d_in[8];
    const float* b_qe      = (const float*)d_in[9];
    const float* W_attn    = (const float*)d_in[10];
    const float* b_attn    = (const float*)d_in[11];
    const float* W_out     = (const float*)d_in[12];
    const float* b_out     = (const float*)d_in[13];
    const float* pe_w1     = (const float*)d_in[14];
    const float* pe_b1     = (const float*)d_in[15];
    const float* pe_g1     = (const float*)d_in[16];
    const float* pe_be1    = (const float*)d_in[17];
    const float* pe_w2     = (const float*)d_in[18];
    const float* pe_b2     = (const float*)d_in[19];
    const float* pe_g2     = (const float*)d_in[20];
    const float* pe_be2    = (const float*)d_in[21];
    const float* W_fin     = (const float*)d_in[22];
    const float* b_fin     = (const float*)d_in[23];
    const float* g_norm    = (const float*)d_in[24];
    const float* b_norm    = (const float*)d_in[25];

    pack_weights<<<80, 256>>>(W_out, pe_w2, W_qe, W_fin);
    detr3d_fused_kernel<<<1024 / QPB, 256>>>(
        query, query_pos, refp, l2i, f0, f1, f2, f3,
        b_qe, W_attn, b_attn, b_out,
        pe_w1, pe_b1, pe_g1, pe_be1, pe_b2, pe_g2, pe_be2,
        b_fin, g_norm, b_norm, (float*)d_out);
}

// round 13
// speedup vs baseline: 2.7175x; 1.0068x over previous
#include <cuda_runtime.h>

#define QPB 2
#define LN_EPS 1e-5f
#define Z_EPS  1e-5f

// k-packed weights: WP[k4*C + c] = {W[(4k4+0)*C+c], ..., W[(4k4+3)*C+c]}
__device__ float4 g_WoutP[64 * 256];
__device__ float4 g_pew2P[64 * 256];
__device__ float4 g_WqeP [16 * 256];
__device__ float4 g_WfinP[64 * 64];

__global__ __launch_bounds__(256)
void pack_weights(const float* __restrict__ Wout, const float* __restrict__ pew2,
                  const float* __restrict__ Wqe,  const float* __restrict__ Wfin) {
    const int bid = blockIdx.x;
    if (bid < 64) {
        const int idx = bid * 256 + threadIdx.x;       // 0 .. 16383
        const int k4 = idx >> 8, c = idx & 255;
        g_WoutP[idx] = make_float4(Wout[(4 * k4 + 0) * 256 + c], Wout[(4 * k4 + 1) * 256 + c],
                                   Wout[(4 * k4 + 2) * 256 + c], Wout[(4 * k4 + 3) * 256 + c]);
        g_pew2P[idx] = make_float4(pew2[(4 * k4 + 0) * 256 + c], pew2[(4 * k4 + 1) * 256 + c],
                                   pew2[(4 * k4 + 2) * 256 + c], pew2[(4 * k4 + 3) * 256 + c]);
    } else {
        const int idx = (bid - 64) * 256 + threadIdx.x; // 0 .. 4095
        {
            const int k4 = idx >> 8, c = idx & 255;     // 16 x 256
            g_WqeP[idx] = make_float4(Wqe[(4 * k4 + 0) * 256 + c], Wqe[(4 * k4 + 1) * 256 + c],
                                      Wqe[(4 * k4 + 2) * 256 + c], Wqe[(4 * k4 + 3) * 256 + c]);
        }
        {
            const int k4 = idx >> 6, c = idx & 63;      // 64 x 64
            g_WfinP[idx] = make_float4(Wfin[(4 * k4 + 0) * 64 + c], Wfin[(4 * k4 + 1) * 64 + c],
                                       Wfin[(4 * k4 + 2) * 64 + c], Wfin[(4 * k4 + 3) * 64 + c]);
        }
    }
}

// Block-wide sum of a float4 across 256 threads.
__device__ __forceinline__ float4 blockSum4(float4 v, float4* red) {
    const int tid  = threadIdx.x;
    const int lane = tid & 31, warp = tid >> 5;
    #pragma unroll
    for (int s = 16; s >= 1; s >>= 1) {
        v.x += __shfl_xor_sync(0xffffffffu, v.x, s);
        v.y += __shfl_xor_sync(0xffffffffu, v.y, s);
        v.z += __shfl_xor_sync(0xffffffffu, v.z, s);
        v.w += __shfl_xor_sync(0xffffffffu, v.w, s);
    }
    if (lane == 0) red[warp] = v;
    __syncthreads();
    if (warp == 0) {
        float4 t = (lane < 8) ? red[lane] : make_float4(0.f, 0.f, 0.f, 0.f);
        #pragma unroll
        for (int s = 4; s >= 1; s >>= 1) {
            t.x += __shfl_xor_sync(0xffffffffu, t.x, s);
            t.y += __shfl_xor_sync(0xffffffffu, t.y, s);
            t.z += __shfl_xor_sync(0xffffffffu, t.z, s);
            t.w += __shfl_xor_sync(0xffffffffu, t.w, s);
        }
        if (lane == 0) red[0] = t;
    }
    __syncthreads();
    float4 r = red[0];
    __syncthreads();
    return r;
}

__global__ __launch_bounds__(256)
void detr3d_fused_kernel(
    const float* __restrict__ query, const float* __restrict__ query_pos,
    const float* __restrict__ refp,  const float* __restrict__ l2i,
    const float* __restrict__ f0, const float* __restrict__ f1,
    const float* __restrict__ f2, const float* __restrict__ f3,
    const float* __restrict__ b_qe,
    const float* __restrict__ W_attn, const float* __restrict__ b_attn,
    const float* __restrict__ b_out,
    const float* __restrict__ pe_w1,  const float* __restrict__ pe_b1,
    const float* __restrict__ pe_g1,  const float* __restrict__ pe_be1,
    const float* __restrict__ pe_b2,
    const float* __restrict__ pe_g2,  const float* __restrict__ pe_be2,
    const float* __restrict__ b_fin,
    const float* __restrict__ g_norm, const float* __restrict__ b_norm,
    float* __restrict__ out)
{
    const int qb   = blockIdx.x * QPB;
    const int tid  = threadIdx.x;
    const int lane = tid & 31, warp = tid >> 5;

    __shared__ __align__(16) float sh_q[QPB][64];
    __shared__ float  sh_ref[QPB][3];
    __shared__ float  sh_qe[QPB][256];
    __shared__ __align__(16) float sh_x[QPB][256];  // gather acc; later h
    __shared__ __align__(16) float sh_p[QPB][256];  // pos MLP hidden
    __shared__ float  sh_part[256];                 // W_fin partials
    __shared__ float4 sh_red[8];
    __shared__ float2 sh_fin[4];
    __shared__ float  sh_w[QPB][24];
    __shared__ int4   sh_gi[QPB][6][4];
    __shared__ float4 sh_gw[QPB][6][4];
    __shared__ int    sh_mask[QPB][6];

    // ---- load q = query + query_pos, reference points
    if (tid < QPB * 64) {
        const int j = tid >> 6, c = tid & 63;
        sh_q[j][c] = query[(qb + j) * 64 + c] + query_pos[(qb + j) * 64 + c];
    }
    if (tid >= 128 && tid < 128 + QPB * 3) {
        const int i = tid - 128;
        sh_ref[i / 3][i % 3] = refp[(qb + i / 3) * 3 + i % 3];
    }
    __syncthreads();

    // ---- qe GEMV (64 -> 256), k-packed weights; thread = channel
    float qe[QPB];
    {
        const float4* u4 = (const float4*)sh_q[0];
        const float4* v4 = (const float4*)sh_q[1];
        float a0 = 0.f, b0 = 0.f, a1 = 0.f, b1 = 0.f;
        #pragma unroll
        for (int k4 = 0; k4 < 16; k4++) {
            const float4 w = g_WqeP[k4 * 256 + tid];
            const float4 u = u4[k4];
            const float4 v = v4[k4];
            a0 = fmaf(w.x, u.x, fmaf(w.y, u.y, a0));
            b0 = fmaf(w.z, u.z, fmaf(w.w, u.w, b0));
            a1 = fmaf(w.x, v.x, fmaf(w.y, v.y, a1));
            b1 = fmaf(w.z, v.z, fmaf(w.w, v.w, b1));
        }
        const float b = __ldg(&b_qe[tid]);
        qe[0] = b + a0 + b0; qe[1] = b + a1 + b1;
        sh_qe[0][tid] = qe[0]; sh_qe[1][tid] = qe[1];
    }

    // ---- projection + tap precompute (threads 0..47; 1 per (j,n,l))
    if (tid < QPB * 24) {
        const int j = tid / 24, r = tid % 24, n = r / 4, l = r % 4;
        const int Hs[4] = { 116, 58, 29, 15 };
        const int Ws[4] = { 200, 100, 50, 25 };
        const float* M = l2i + n * 16;
        const float rx = sh_ref[j][0], ry = sh_ref[j][1], rz = sh_ref[j][2];
        float c0 = M[0] * rx + M[1] * ry + M[2]  * rz + M[3];
        float c1 = M[4] * rx + M[5] * ry + M[6]  * rz + M[7];
        float c2 = M[8] * rx + M[9] * ry + M[10] * rz + M[11];
        bool front = c2 > Z_EPS;
        float zc = fmaxf(c2, Z_EPS);
        float gx = (c0 / zc / 1600.0f - 0.5f) * 2.0f;
        float gy = (c1 / zc / 928.0f  - 0.5f) * 2.0f;
        bool inb = (gx > -1.0f) && (gx < 1.0f) && (gy > -1.0f) && (gy < 1.0f);
        if (l == 0) sh_mask[j][n] = (front && inb) ? 1 : 0;

        const int W = Ws[l], H = Hs[l];
        float x = ((gx + 1.0f) * (float)W - 1.0f) * 0.5f;
        float y = ((gy + 1.0f) * (float)H - 1.0f) * 0.5f;
        float fx0 = floorf(x), fy0 = floorf(y);
        int x0 = (int)fx0, y0 = (int)fy0;
        float wx1 = x - fx0, wx0 = 1.0f - wx1;
        float wy1 = y - fy0, wy0 = 1.0f - wy1;
        float vx0 = (x0 >= 0 && x0 < W) ? 1.0f : 0.0f;
        float vx1 = (x0 + 1 >= 0 && x0 + 1 < W) ? 1.0f : 0.0f;
        float vy0 = (y0 >= 0 && y0 < H) ? 1.0f : 0.0f;
        float vy1 = (y0 + 1 >= 0 && y0 + 1 < H) ? 1.0f : 0.0f;
        int cx0 = min(max(x0, 0), W - 1);
        int cx1 = min(max(x0 + 1, 0), W - 1);
        int cy0 = min(max(y0, 0), H - 1);
        int cy1 = min(max(y0 + 1, 0), H - 1);
        sh_gi[j][n][l] = make_int4(cy0 * W + cx0, cy0 * W + cx1,
                                   cy1 * W + cx0, cy1 * W + cx1);
        sh_gw[j][n][l] = make_float4(wy0 * wx0 * vy0 * vx0, wy0 * wx1 * vy0 * vx1,
                                     wy1 * wx0 * vy1 * vx0, wy1 * wx1 * vy1 * vx1);
    }
    __syncthreads();

    // ---- attw: warp-split GEMV; warp w owns outputs {w, w+8, w+16}
    {
        float acc[3][QPB];
        #pragma unroll
        for (int i = 0; i < 3; i++)
            #pragma unroll
            for (int j = 0; j < QPB; j++) acc[i][j] = 0.0f;
        #pragma unroll
        for (int kk = 0; kk < 8; kk++) {
            const int k = lane + 32 * kk;
            const float q0 = sh_qe[0][k];
            const float q1 = sh_qe[1][k];
            #pragma unroll
            for (int i = 0; i < 3; i++) {
                const float wv = __ldg(&W_attn[k * 24 + warp + 8 * i]);
                acc[i][0] = fmaf(q0, wv, acc[i][0]);
                acc[i][1] = fmaf(q1, wv, acc[i][1]);
            }
        }
        #pragma unroll
        for (int i = 0; i < 3; i++)
            #pragma unroll
            for (int j = 0; j < QPB; j++) {
                #pragma unroll
                for (int s = 16; s >= 1; s >>= 1)
                    acc[i][j] += __shfl_xor_sync(0xffffffffu, acc[i][j], s);
            }
        if (lane == 0) {
            #pragma unroll
            for (int i = 0; i < 3; i++) {
                const int o = warp + 8 * i;
                const float b = __ldg(&b_attn[o]);
                sh_w[0][o] = 1.0f / (1.0f + expf(-(acc[i][0] + b)));
                sh_w[1][o] = 1.0f / (1.0f + expf(-(acc[i][1] + b)));
            }
        }
    }
    __syncthreads();

    // ---- prefetch first 8 W_out chunks (independent of gather)
    float4 pw[8];
    #pragma unroll
    for (int i = 0; i < 8; i++) pw[i] = g_WoutP[i * 256 + tid];

    // ---- masked bilinear gather (precomputed taps). thread = channel.
    {
        const float* fps[4] = { f0, f1, f2, f3 };
        const int HWs[4] = { 116 * 200, 58 * 100, 29 * 50, 15 * 25 };
        float acc[QPB];
        #pragma unroll
        for (int j = 0; j < QPB; j++) acc[j] = 0.0f;
        #pragma unroll
        for (int j = 0; j < QPB; j++) {
            for (int n = 0; n < 6; n++) {
                if (!sh_mask[j][n]) continue;
                #pragma unroll
                for (int l = 0; l < 4; l++) {
                    const int4   o = sh_gi[j][n][l];
                    const float4 w = sh_gw[j][n][l];
                    const float* fb = fps[l] + (size_t)(n * 256 + tid) * (size_t)HWs[l];
                    float v = w.x * __ldg(fb + o.x)
                            + w.y * __ldg(fb + o.y)
                            + w.z * __ldg(fb + o.z)
                            + w.w * __ldg(fb + o.w);
                    acc[j] = fmaf(sh_w[j][n * 4 + l], v, acc[j]);
                }
            }
        }
        sh_x[0][tid] = acc[0]; sh_x[1][tid] = acc[1];
    }
    __syncthreads();

    // ---- W_out GEMV (256 -> 256), k-packed; first 8 chunks from prefetch
    float ov[QPB];
    {
        const float4* u4 = (const float4*)sh_x[0];
        const float4* v4 = (const float4*)sh_x[1];
        float a0 = 0.f, b0 = 0.f, a1 = 0.f, b1 = 0.f;
        #pragma unroll
        for (int k4 = 0; k4 < 8; k4++) {
            const float4 w = pw[k4];
            const float4 u = u4[k4];
            const float4 v = v4[k4];
            a0 = fmaf(w.x, u.x, fmaf(w.y, u.y, a0));
            b0 = fmaf(w.z, u.z, fmaf(w.w, u.w, b0));
            a1 = fmaf(w.x, v.x, fmaf(w.y, v.y, a1));
            b1 = fmaf(w.z, v.z, fmaf(w.w, v.w, b1));
        }
        #pragma unroll 16
        for (int k4 = 8; k4 < 64; k4++) {
            const float4 w = g_WoutP[k4 * 256 + tid];
            const float4 u = u4[k4];
            const float4 v = v4[k4];
            a0 = fmaf(w.x, u.x, fmaf(w.y, u.y, a0));
            b0 = fmaf(w.z, u.z, fmaf(w.w, u.w, b0));
            a1 = fmaf(w.x, v.x, fmaf(w.y, v.y, a1));
            b1 = fmaf(w.z, v.z, fmaf(w.w, v.w, b1));
        }
        const float b = __ldg(&b_out[tid]);
        ov[0] = b + a0 + b0; ov[1] = b + a1 + b1;
    }

    // ---- prefetch first 8 pe_w2 chunks; hidden behind pos-stage-1 reduction
    float4 pp[8];
    #pragma unroll
    for (int i = 0; i < 8; i++) pp[i] = g_pew2P[i * 256 + tid];

    // ---- positional MLP stage 1: ref @ pe_w1 + pe_b1 -> LN -> relu
    {
        const float w1 = __ldg(&pe_w1[tid]);
        const float w2 = __ldg(&pe_w1[256 + tid]);
        const float w3 = __ldg(&pe_w1[512 + tid]);
        const float b  = __ldg(&pe_b1[tid]);
        float p[QPB];
        #pragma unroll
        for (int j = 0; j < QPB; j++)
            p[j] = b + sh_ref[j][0] * w1 + sh_ref[j][1] * w2 + sh_ref[j][2] * w3;
        float4 s = blockSum4(make_float4(p[0], p[1], p[0]*p[0], p[1]*p[1]), sh_red);
        const float g = __ldg(&pe_g1[tid]), be = __ldg(&pe_be1[tid]);
        {
            float m = s.x * (1.0f / 256.0f);
            float var = s.z * (1.0f / 256.0f) - m * m;
            sh_p[0][tid] = fmaxf((p[0] - m) * rsqrtf(var + LN_EPS) * g + be, 0.0f);
        }
        {
            float m = s.y * (1.0f / 256.0f);
            float var = s.w * (1.0f / 256.0f) - m * m;
            sh_p[1][tid] = fmaxf((p[1] - m) * rsqrtf(var + LN_EPS) * g + be, 0.0f);
        }
    }
    __syncthreads();

    // ---- pe_w2 GEMV (256 -> 256), k-packed; first 8 chunks from prefetch
    float p2[QPB];
    {
        const float4* u4 = (const float4*)sh_p[0];
        const float4* v4 = (const float4*)sh_p[1];
        float a0 = 0.f, b0 = 0.f, a1 = 0.f, b1 = 0.f;
        #pragma unroll
        for (int k4 = 0; k4 < 8; k4++) {
            const float4 w = pp[k4];
            const float4 u = u4[k4];
            const float4 v = v4[k4];
            a0 = fmaf(w.x, u.x, fmaf(w.y, u.y, a0));
            b0 = fmaf(w.z, u.z, fmaf(w.w, u.w, b0));
            a1 = fmaf(w.x, v.x, fmaf(w.y, v.y, a1));
            b1 = fmaf(w.z, v.z, fmaf(w.w, v.w, b1));
        }
        #pragma unroll 16
        for (int k4 = 8; k4 < 64; k4++) {
            const float4 w = g_pew2P[k4 * 256 + tid];
            const float4 u = u4[k4];
            const float4 v = v4[k4];
            a0 = fmaf(w.x, u.x, fmaf(w.y, u.y, a0));
            b0 = fmaf(w.z, u.z, fmaf(w.w, u.w, b0));
            a1 = fmaf(w.x, v.x, fmaf(w.y, v.y, a1));
            b1 = fmaf(w.z, v.z, fmaf(w.w, v.w, b1));
        }
        const float b = __ldg(&pe_b2[tid]);
        p2[0] = b + a0 + b0; p2[1] = b + a1 + b1;

        float4 s = blockSum4(make_float4(p2[0], p2[1], p2[0]*p2[0], p2[1]*p2[1]), sh_red);
        const float g = __ldg(&pe_g2[tid]), be = __ldg(&pe_be2[tid]);
        {
            float m = s.x * (1.0f / 256.0f);
            float var = s.z * (1.0f / 256.0f) - m * m;
            p2[0] = fmaxf((p2[0] - m) * rsqrtf(var + LN_EPS) * g + be, 0.0f);
        }
        {
            float m = s.y * (1.0f / 256.0f);
            float var = s.w * (1.0f / 256.0f) - m * m;
            p2[1] = fmaxf((p2[1] - m) * rsqrtf(var + LN_EPS) * g + be, 0.0f);
        }
    }

    // ---- h = ov + residual(qe) + pos
    sh_x[0][tid] = ov[0] + qe[0] + p2[0];
    sh_x[1][tid] = ov[1] + qe[1] + p2[1];
    __syncthreads();

    // ---- W_fin GEMV (256 -> 64), k-packed, split-k x2. tid = p*128 + j*64 + c
    {
        const int p = tid >> 7;
        const int j = (tid >> 6) & 1;
        const int c = tid & 63;
        const float4* x4 = (const float4*)sh_x[j] + p * 32;
        const float4* wp = &g_WfinP[p * 32 * 64];
        float a = 0.f, b = 0.f;
        #pragma unroll 8
        for (int k4 = 0; k4 < 32; k4++) {
            const float4 w = wp[k4 * 64 + c];
            const float4 u = x4[k4];
            a = fmaf(w.x, u.x, fmaf(w.y, u.y, a));
            b = fmaf(w.z, u.z, fmaf(w.w, u.w, b));
        }
        sh_part[tid] = a + b;
    }
    __syncthreads();

    // ---- combine halves, LN over 64 channels, write out (threads 0..127)
    float y = 0.0f;
    if (tid < 128) {
        const int c = tid & 63;
        y = __ldg(&b_fin[c]) + sh_part[tid] + sh_part[128 + tid];
        float sx = y, sxx = y * y;
        #pragma unroll
        for (int s = 16; s >= 1; s >>= 1) {
            sx  += __shfl_xor_sync(0xffffffffu, sx,  s);
            sxx += __shfl_xor_sync(0xffffffffu, sxx, s);
        }
        if (lane == 0) sh_fin[warp] = make_float2(sx, sxx);
    }
    __syncthreads();
    if (tid < 128) {
        const int c = tid & 63;
        const int j = tid >> 6;
        float2 a = sh_fin[j * 2];
        float2 b = sh_fin[j * 2 + 1];
        float m   = (a.x + b.x) * (1.0f / 64.0f);
        float var = (a.y + b.y) * (1.0f / 64.0f) - m * m;
        out[(qb + j) * 64 + c] =
            (y - m) * rsqrtf(var + LN_EPS) * __ldg(&g_norm[c]) + __ldg(&b_norm[c]);
    }
}

extern "C" void kernel_launch(void* const* d_in, const int* in_sizes, int n_in,
                              void* d_out, int out_size) {
    (void)in_sizes; (void)n_in; (void)out_size;
    const float* query     = (const float*)d_in[0];
    const float* query_pos = (const float*)d_in[1];
    const float* refp      = (const float*)d_in[2];
    const float* l2i       = (const float*)d_in[3];
    const float* f0        = (const float*)d_in[4];
    const float* f1        = (const float*)d_in[5];
    const float* f2        = (const float*)d_in[6];
    const float* f3        = (const float*)d_in[7];
    const float* W_qe      = (const float*)d_in[8];
    const float* b_qe      = (const float*)d_in[9];
    const float* W_attn    = (const float*)d_in[10];
    const float* b_attn    = (const float*)d_in[11];
    const float* W_out     = (const float*)d_in[12];
    const float* b_out     = (const float*)d_in[13];
    const float* pe_w1     = (const float*)d_in[14];
    const float* pe_b1     = (const float*)d_in[15];
    const float* pe_g1     = (const float*)d_in[16];
    const float* pe_be1    = (const float*)d_in[17];
    const float* pe_w2     = (const float*)d_in[18];
    const float* pe_b2     = (const float*)d_in[19];
    const float* pe_g2     = (const float*)d_in[20];
    const float* pe_be2    = (const float*)d_in[21];
    const float* W_fin     = (const float*)d_in[22];
    const float* b_fin     = (const float*)d_in[23];
    const float* g_norm    = (const float*)d_in[24];
    const float* b_norm    = (const float*)d_in[25];

    pack_weights<<<80, 256>>>(W_out, pe_w2, W_qe, W_fin);
    detr3d_fused_kernel<<<1024 / QPB, 256>>>(
        query, query_pos, refp, l2i, f0, f1, f2, f3,
        b_qe, W_attn, b_attn, b_out,
        pe_w1, pe_b1, pe_g1, pe_be1, pe_b2, pe_g2, pe_be2,
        b_fin, g_norm, b_norm, (float*)d_out);
}